// round 1
// baseline (speedup 1.0000x reference)
#include <cuda_runtime.h>
#include <cuda_bf16.h>
#include <cstdint>

// Problem constants
#define Bsz 64
#define Tt  512
#define Ee  512
#define Hh  512
#define G4  2048          // 4*H
#define NC  64            // CTAs per direction in recurrence
#define CH  8             // hidden units per CTA (H / NC)
#define HSS 516           // padded SMEM stride for h  (516 % 32 == 4 -> conflict-free)
#define REC_THREADS 256
#define REC_SMEM ((512*32 + 64*HSS)*4)

// ---------------- scratch (static device memory; no allocation) ----------------
__device__ float g_x  [(size_t)Bsz*Tt*Ee];        //  64 MB embedded input
__device__ float g_xz0[(size_t)Bsz*Tt*G4];        // 256 MB input-proj (fwd)
__device__ float g_xz1[(size_t)Bsz*Tt*G4];        // 256 MB input-proj (bwd)
__device__ float g_l1 [(size_t)Bsz*Tt*2*Hh];      // 128 MB layer-1 concat output
__device__ float g_hbuf[2*2*Bsz*Hh];              // [dir][parity][B][H] h state
__device__ int   g_cnt[4];                        // per (layer,dir) barrier counters

// ---------------- f32x2 packed-FMA helpers (B300 FFMA2) ----------------
__device__ __forceinline__ void fma2(unsigned long long &d, unsigned long long a,
                                     unsigned long long b) {
    asm("fma.rn.f32x2 %0, %1, %2, %0;" : "+l"(d) : "l"(a), "l"(b));
}
__device__ __forceinline__ unsigned long long pack2(float lo, float hi) {
    unsigned long long r;
    asm("mov.b64 %0, {%1, %2};" : "=l"(r) : "f"(lo), "f"(hi));
    return r;
}
__device__ __forceinline__ unsigned long long dup2(float x) { return pack2(x, x); }
__device__ __forceinline__ float2 unpack2(unsigned long long v) {
    float2 r;
    asm("mov.b64 {%0, %1}, %2;" : "=f"(r.x), "=f"(r.y) : "l"(v));
    return r;
}
__device__ __forceinline__ float sigm(float x) { return 1.0f / (1.0f + expf(-x)); }

// ---------------- init: zero h state (+ counters on full init) ----------------
__global__ void k_init(int full) {
    int i = blockIdx.x * blockDim.x + threadIdx.x;      // 128*256 = 32768 threads
    float4 z = make_float4(0.f, 0.f, 0.f, 0.f);
    if (i < 2*2*Bsz*Hh/4) ((float4*)g_hbuf)[i] = z;
    if (full && i < 4) g_cnt[i] = 0;
}

// ---------------- embedding gather: x[b,t,:] = emb[ids[b,t],:] ----------------
__global__ void k_gather(const int* __restrict__ ids, const float* __restrict__ emb) {
    int i = blockIdx.x * blockDim.x + threadIdx.x;      // float4 index, 4194304 total
    int bt = i >> 7;                                     // / (E/4 = 128)
    int c  = i & 127;
    int id = __ldg(&ids[bt]);
    ((float4*)g_x)[i] = __ldg((const float4*)emb + (size_t)id * 128 + c);
}

// ---------------- SGEMM (fp32, FFMA2):  Y[M,2048] = X[M,K] @ W[K,2048] + bias ----------------
// BM=BN=64, BK=16, 128 threads, thread tile 4x8.
__global__ void __launch_bounds__(128)
k_sgemm(const float* __restrict__ X, const float* __restrict__ W,
        const float* __restrict__ bias, float* __restrict__ Y, int K) {
    const int N = 2048;
    __shared__ float As[16][64];   // transposed: As[k][m]
    __shared__ float Bs[16][64];

    const int tid = threadIdx.x;
    const int bm = blockIdx.y * 64;
    const int bn = blockIdx.x * 64;

    const int a_m = tid >> 2;            // 0..31
    const int a_k = (tid & 3) * 4;       // 0,4,8,12
    const int b_k = tid >> 4;            // 0..7
    const int b_n = (tid & 15) * 4;      // 0..60
    const int mt  = (tid & 15) * 4;      // thread tile m base
    const int nt  = (tid >> 4) * 8;      // thread tile n base

    unsigned long long acc[4][4];
#pragma unroll
    for (int i = 0; i < 4; i++)
#pragma unroll
        for (int j = 0; j < 4; j++) acc[i][j] = 0ULL;

    for (int k0 = 0; k0 < K; k0 += 16) {
        float4 av0 = *(const float4*)&X[(size_t)(bm + a_m)      * K + k0 + a_k];
        float4 av1 = *(const float4*)&X[(size_t)(bm + a_m + 32) * K + k0 + a_k];
        float4 bv0 = *(const float4*)&W[(size_t)(k0 + b_k)     * N + bn + b_n];
        float4 bv1 = *(const float4*)&W[(size_t)(k0 + b_k + 8) * N + bn + b_n];
        __syncthreads();
        As[a_k+0][a_m] = av0.x; As[a_k+1][a_m] = av0.y;
        As[a_k+2][a_m] = av0.z; As[a_k+3][a_m] = av0.w;
        As[a_k+0][a_m+32] = av1.x; As[a_k+1][a_m+32] = av1.y;
        As[a_k+2][a_m+32] = av1.z; As[a_k+3][a_m+32] = av1.w;
        *(float4*)&Bs[b_k][b_n]     = bv0;
        *(float4*)&Bs[b_k + 8][b_n] = bv1;
        __syncthreads();
#pragma unroll
        for (int k = 0; k < 16; k++) {
            float4 a = *(const float4*)&As[k][mt];
            ulonglong2 u0 = *(const ulonglong2*)&Bs[k][nt];
            ulonglong2 u1 = *(const ulonglong2*)&Bs[k][nt + 4];
            unsigned long long d0 = dup2(a.x), d1 = dup2(a.y),
                               d2 = dup2(a.z), d3 = dup2(a.w);
            fma2(acc[0][0], d0, u0.x); fma2(acc[0][1], d0, u0.y);
            fma2(acc[0][2], d0, u1.x); fma2(acc[0][3], d0, u1.y);
            fma2(acc[1][0], d1, u0.x); fma2(acc[1][1], d1, u0.y);
            fma2(acc[1][2], d1, u1.x); fma2(acc[1][3], d1, u1.y);
            fma2(acc[2][0], d2, u0.x); fma2(acc[2][1], d2, u0.y);
            fma2(acc[2][2], d2, u1.x); fma2(acc[2][3], d2, u1.y);
            fma2(acc[3][0], d3, u0.x); fma2(acc[3][1], d3, u0.y);
            fma2(acc[3][2], d3, u1.x); fma2(acc[3][3], d3, u1.y);
        }
    }
#pragma unroll
    for (int i = 0; i < 4; i++) {
        int row = bm + mt + i;
        float* yr = Y + (size_t)row * N + bn + nt;
#pragma unroll
        for (int j = 0; j < 4; j++) {
            float2 v = unpack2(acc[i][j]);
            int c = bn + nt + j * 2;
            yr[j*2]     = v.x + bias[c];
            yr[j*2 + 1] = v.y + bias[c + 1];
        }
    }
}

// ---------------- persistent bidirectional LSTM recurrence ----------------
// grid = 128 CTAs: blockIdx/64 = dir (0 fwd, 1 bwd), blockIdx%64 = hidden chunk.
// Per CTA: U slice (512 x 32 gate-cols, gate-interleaved) resident in SMEM;
// h_prev (64x512) staged to SMEM each step; c state in registers.
// Inter-CTA sync: per-direction monotonic atomic counter, double-buffered h.
__global__ void __launch_bounds__(REC_THREADS, 1)
k_rec(const float* __restrict__ xzf, const float* __restrict__ xzb,
      const float* __restrict__ Uf,  const float* __restrict__ Ub,
      float* __restrict__ hs_out, float* st_out, int layer) {
    extern __shared__ float sm[];
    float* Us = sm;               // [512][32] packed: k*32 + jj*4 + gate
    float* Hs = sm + 512 * 32;    // [64][HSS]

    const int dir = blockIdx.x >> 6;
    const int cid = blockIdx.x & 63;
    const float* xz = dir ? xzb : xzf;
    const float* U  = dir ? Ub  : Uf;
    int* cnt = &g_cnt[layer * 2 + dir];
    const int jbase = cid * CH;
    const int tid = threadIdx.x;

    // pack U slice into SMEM, gate-interleaved so each thread's 4 contiguous
    // columns are the i,f,g,o rows of ONE hidden unit
    for (int idx = tid; idx < 512 * 32; idx += REC_THREADS) {
        int k = idx >> 5, cc = idx & 31;
        int jj = cc >> 2, g = cc & 3;
        Us[idx] = U[(size_t)k * G4 + g * Hh + jbase + jj];
    }

    const int bp = tid >> 3;          // 0..31 -> batch pair
    const int jj = tid & 7;           // local hidden unit
    const int b0 = bp * 2, b1 = b0 + 1;
    const int jg = jbase + jj;
    float c0 = 0.f, c1 = 0.f;

    float* HB0 = g_hbuf + (size_t)dir * 2 * Bsz * Hh;
    float* HB1 = HB0 + Bsz * Hh;
    const float* uptr = Us + jj * 4;
    __syncthreads();

    for (int s = 0; s < Tt; ++s) {
        const int tt = dir ? (Tt - 1 - s) : s;
        const float* hp = (s & 1) ? HB1 : HB0;
        float*       hn = (s & 1) ? HB0 : HB1;

        // stage h_prev (L2 -> SMEM), L1-bypassed for cross-CTA coherence
        for (int idx = tid * 4; idx < Bsz * Hh; idx += REC_THREADS * 4) {
            float4 v = __ldcg((const float4*)(hp + idx));
            int b = idx >> 9, k = idx & 511;
            *(float4*)&Hs[b * HSS + k] = v;
        }
        __syncthreads();

        const float* xzp = xz + (size_t)tt * G4 + jg;
        size_t o0 = (size_t)b0 * Tt * G4, o1 = (size_t)b1 * Tt * G4;
        unsigned long long a001 = pack2(__ldcs(xzp + o0),        __ldcs(xzp + o0 + 512));
        unsigned long long a023 = pack2(__ldcs(xzp + o0 + 1024), __ldcs(xzp + o0 + 1536));
        unsigned long long a101 = pack2(__ldcs(xzp + o1),        __ldcs(xzp + o1 + 512));
        unsigned long long a123 = pack2(__ldcs(xzp + o1 + 1024), __ldcs(xzp + o1 + 1536));

#pragma unroll 8
        for (int k = 0; k < Hh; ++k) {
            float h0 = Hs[b0 * HSS + k];
            float h1 = Hs[b1 * HSS + k];
            ulonglong2 uu = *(const ulonglong2*)(uptr + k * 32);
            unsigned long long h00 = dup2(h0), h11 = dup2(h1);
            fma2(a001, h00, uu.x); fma2(a023, h00, uu.y);
            fma2(a101, h11, uu.x); fma2(a123, h11, uu.y);
        }

        float2 zif0 = unpack2(a001), zgo0 = unpack2(a023);
        float2 zif1 = unpack2(a101), zgo1 = unpack2(a123);
        float i0 = sigm(zif0.x), f0 = sigm(zif0.y);
        float gg0 = tanhf(zgo0.x), o0g = sigm(zgo0.y);
        c0 = f0 * c0 + i0 * gg0;
        float h0n = o0g * tanhf(c0);
        float i1 = sigm(zif1.x), f1 = sigm(zif1.y);
        float gg1 = tanhf(zgo1.x), o1g = sigm(zgo1.y);
        c1 = f1 * c1 + i1 * gg1;
        float h1n = o1g * tanhf(c1);

        hn[b0 * Hh + jg] = h0n;
        hn[b1 * Hh + jg] = h1n;
        hs_out[((size_t)b0 * Tt + tt) * 1024 + dir * Hh + jg] = h0n;
        hs_out[((size_t)b1 * Tt + tt) * 1024 + dir * Hh + jg] = h1n;
        if (st_out != nullptr && s == Tt - 1) {
            st_out[b0 * 1024 + dir * Hh + jg] = h0n;               // state_h
            st_out[b1 * 1024 + dir * Hh + jg] = h1n;
            st_out[Bsz * 1024 + b0 * 1024 + dir * Hh + jg] = c0;   // state_c
            st_out[Bsz * 1024 + b1 * 1024 + dir * Hh + jg] = c1;
        }

        // inter-CTA step barrier (per direction)
        __threadfence();
        __syncthreads();
        if (tid == 0) {
            atomicAdd(cnt, 1);
            const int target = NC * (s + 1);
            while (*(volatile int*)cnt < target) __nanosleep(32);
        }
        __syncthreads();
        __threadfence();
    }
}

// ---------------- launch sequence ----------------
extern "C" void kernel_launch(void* const* d_in, const int* in_sizes, int n_in,
                              void* d_out, int out_size) {
    const int*   ids = (const int*)d_in[0];
    const float* emb = (const float*)d_in[1];
    const float *W1f = (const float*)d_in[2],  *U1f = (const float*)d_in[3],
                *b1f = (const float*)d_in[4];
    const float *W1b = (const float*)d_in[5],  *U1b = (const float*)d_in[6],
                *b1b = (const float*)d_in[7];
    const float *W2f = (const float*)d_in[8],  *U2f = (const float*)d_in[9],
                *b2f = (const float*)d_in[10];
    const float *W2b = (const float*)d_in[11], *U2b = (const float*)d_in[12],
                *b2b = (const float*)d_in[13];
    float* out = (float*)d_out;

    float *px, *pxz0, *pxz1, *pl1;
    cudaGetSymbolAddress((void**)&px,   g_x);
    cudaGetSymbolAddress((void**)&pxz0, g_xz0);
    cudaGetSymbolAddress((void**)&pxz1, g_xz1);
    cudaGetSymbolAddress((void**)&pl1,  g_l1);

    cudaFuncSetAttribute(k_rec, cudaFuncAttributeMaxDynamicSharedMemorySize, REC_SMEM);

    k_init<<<128, 256>>>(1);
    k_gather<<<16384, 256>>>(ids, emb);

    dim3 gg(G4 / 64, (Bsz * Tt) / 64);   // (32, 512)
    // layer 1 input projections
    k_sgemm<<<gg, 128>>>(px, W1f, b1f, pxz0, Ee);
    k_sgemm<<<gg, 128>>>(px, W1b, b1b, pxz1, Ee);
    // layer 1 recurrence (both directions) -> g_l1
    k_rec<<<2 * NC, REC_THREADS, REC_SMEM>>>(pxz0, pxz1, U1f, U1b, pl1, nullptr, 0);
    // reset h state for layer 2
    k_init<<<128, 256>>>(0);
    // layer 2 input projections (K = 2H)
    k_sgemm<<<gg, 128>>>(pl1, W2f, b2f, pxz0, 2 * Hh);
    k_sgemm<<<gg, 128>>>(pl1, W2b, b2b, pxz1, 2 * Hh);
    // layer 2 recurrence -> encoder_output + states directly in d_out
    k_rec<<<2 * NC, REC_THREADS, REC_SMEM>>>(pxz0, pxz1, U2f, U2b, out,
                                             out + (size_t)Bsz * Tt * 1024, 1);
}